// round 2
// baseline (speedup 1.0000x reference)
#include <cuda_runtime.h>
#include <math.h>

#define BATCH 2
#define NP    4096
#define HH    128
#define WW    128
#define KK    8
#define RAD   0.05f
#define RAD2  (RAD * RAD)
#define TILE  16
#define TX    (WW / TILE)   // 8
#define TYN   (HH / TILE)   // 8

#define ZINF 3.0e38f

// Dynamic smem: candidate list, capacity NP (overflow impossible)
#define SMEM_BYTES (NP * (int)sizeof(float4))

__global__ void __launch_bounds__(256) raster_fused_kernel(
        const float* __restrict__ pts,
        const float* __restrict__ Rm,
        const float* __restrict__ Tv,
        const float* __restrict__ Fc,
        float* __restrict__ out) {
    extern __shared__ float4 sc[];
    __shared__ int s_n;

    const int tx = blockIdx.x, ty = blockIdx.y, b = blockIdx.z;
    const int tid = threadIdx.x;

    if (tid == 0) s_n = 0;
    __syncthreads();

    // Uniform per-batch camera params (L2/const-path broadcast loads)
    const float* Rb = Rm + b * 9;
    const float* Tb = Tv + b * 3;
    const float r00 = Rb[0], r01 = Rb[1], r02 = Rb[2];
    const float r10 = Rb[3], r11 = Rb[4], r12 = Rb[5];
    const float r20 = Rb[6], r21 = Rb[7], r22 = Rb[8];
    const float t0 = Tb[0], t1 = Tb[1], t2 = Tb[2];
    const float f  = Fc[b];

    // Tile NDC bounds (gx decreases with pixel x): pixel center gx = 1 - (ix+0.5)/64
    const float gx_hi = 1.0f - (float)(TILE * tx + 0) * (1.0f / 64.0f) - 0.5f * (1.0f / 64.0f);
    const float gx_lo = 1.0f - (float)(TILE * tx + TILE - 1) * (1.0f / 64.0f) - 0.5f * (1.0f / 64.0f);
    const float gy_hi = 1.0f - (float)(TILE * ty + 0) * (1.0f / 64.0f) - 0.5f * (1.0f / 64.0f);
    const float gy_lo = 1.0f - (float)(TILE * ty + TILE - 1) * (1.0f / 64.0f) - 0.5f * (1.0f / 64.0f);
    const float bx_lo = gx_lo - RAD, bx_hi = gx_hi + RAD;
    const float by_lo = gy_lo - RAD, by_hi = gy_hi + RAD;

    // ---- Phase 1: transform all points of this batch; bin into shared list ----
    const float* pb = pts + (size_t)b * NP * 3;
#pragma unroll 4
    for (int p = tid; p < NP; p += 256) {
        float p0 = pb[3 * p + 0];
        float p1 = pb[3 * p + 1];
        float p2 = pb[3 * p + 2];

        // row-vector: v[j] = sum_i p[i]*R[i][j] + T[j]
        float xv = p0 * r00 + p1 * r10 + p2 * r20 + t0;
        float yv = p0 * r01 + p1 * r11 + p2 * r21 + t1;
        float zv = p0 * r02 + p1 * r12 + p2 * r22 + t2;

        float x = f * xv / zv;   // IEEE div, matches reference
        float y = f * yv / zv;

        if (zv > 0.0f && x > bx_lo && x < bx_hi && y > by_lo && y < by_hi) {
            int pos = atomicAdd(&s_n, 1);
            sc[pos] = make_float4(x, y, zv, (float)p);
        }
    }
    __syncthreads();
    const int n = s_n;

    // ---- Phase 2: per-pixel exact test + register-resident top-8 by z ----
    const int lx = tid & 15, ly = tid >> 4;
    const int px = tx * TILE + lx;
    const int py = ty * TILE + ly;
    const float gx = 1.0f - (px + 0.5f) * (1.0f / 64.0f);
    const float gy = 1.0f - (py + 0.5f) * (1.0f / 64.0f);

    float zb[KK], db[KK];
    float ib[KK];
#pragma unroll
    for (int k = 0; k < KK; k++) { zb[k] = ZINF; db[k] = -1.0f; ib[k] = -1.0f; }

    for (int j = 0; j < n; j++) {
        float4 c = sc[j];                 // LDS.128 broadcast
        float dx = gx - c.x;
        float dy = gy - c.y;
        float d2 = fmaf(dx, dx, dy * dy);
        if (d2 < RAD2 && c.z < zb[KK - 1]) {
            float zi = c.z, di = d2, ii = c.w;
#pragma unroll
            for (int k = 0; k < KK; k++) {
                if (zi < zb[k]) {
                    float t;
                    t = zb[k]; zb[k] = zi; zi = t;
                    t = db[k]; db[k] = di; di = t;
                    t = ib[k]; ib[k] = ii; ii = t;
                }
            }
        }
    }

    // ---- Output: [idx | zbuf | dists], each [B,H,W,K] ----
    const int N = BATCH * HH * WW * KK;
    const int obase = ((b * HH + py) * WW + px) * KK;
#pragma unroll
    for (int k = 0; k < KK; k++) {
        bool v = zb[k] < ZINF;
        out[obase + k]         = v ? ib[k] : -1.0f;
        out[N + obase + k]     = v ? zb[k] : -1.0f;
        out[2 * N + obase + k] = v ? db[k] : -1.0f;
    }
}

extern "C" void kernel_launch(void* const* d_in, const int* in_sizes, int n_in,
                              void* d_out, int out_size) {
    const float* pts = (const float*)d_in[0];
    const float* Rm  = (const float*)d_in[1];
    const float* Tv  = (const float*)d_in[2];
    const float* Fc  = (const float*)d_in[3];
    float* out = (float*)d_out;

    cudaFuncSetAttribute(raster_fused_kernel,
                         cudaFuncAttributeMaxDynamicSharedMemorySize, SMEM_BYTES);
    raster_fused_kernel<<<dim3(TX, TYN, BATCH), 256, SMEM_BYTES>>>(pts, Rm, Tv, Fc, out);
}

// round 3
// speedup vs baseline: 1.3089x; 1.3089x over previous
#include <cuda_runtime.h>
#include <math.h>

#define BATCH 2
#define NP    4096
#define HH    128
#define WW    128
#define KK    8
#define RAD   0.05f
#define RAD2  (RAD * RAD)
#define TILE  16
#define TX    (WW / TILE)   // 8
#define TYN   (HH / TILE)   // 8
#define NTILES (TX * TYN)   // 64
#define CHUNK 512

#define ZINF 3.0e38f

// Global scratch (no cudaMalloc allowed). Lists hold full candidate records.
__device__ int    g_cnt[BATCH * NTILES];            // zero-init at load; re-zeroed by raster
__device__ float4 g_list[BATCH * NTILES * NP];      // 8 MB

// ---------------------------------------------------------------------------
// Kernel A: world->view->NDC transform + scatter float4 record into tiles
// ---------------------------------------------------------------------------
__global__ void transform_bin_kernel(const float* __restrict__ pts,
                                     const float* __restrict__ Rm,
                                     const float* __restrict__ Tv,
                                     const float* __restrict__ Fc) {
    int t = blockIdx.x * blockDim.x + threadIdx.x;
    if (t >= BATCH * NP) return;
    int b = t / NP;
    int p = t - b * NP;

    float p0 = pts[t * 3 + 0];
    float p1 = pts[t * 3 + 1];
    float p2 = pts[t * 3 + 2];
    const float* Rb = Rm + b * 9;
    const float* Tb = Tv + b * 3;

    // row-vector convention: v[j] = sum_i p[i] * R[i][j] + T[j]
    float xv = p0 * Rb[0] + p1 * Rb[3] + p2 * Rb[6] + Tb[0];
    float yv = p0 * Rb[1] + p1 * Rb[4] + p2 * Rb[7] + Tb[1];
    float zv = p0 * Rb[2] + p1 * Rb[5] + p2 * Rb[8] + Tb[2];

    float f = Fc[b];
    float x = f * xv / zv;   // IEEE div, matches reference
    float y = f * yv / zv;

    if (!(zv > 0.0f)) return;

    // pixel ix covered iff |gx(ix) - x| < r, gx(ix) = 1 - (ix+0.5)/64
    float lox = 64.0f * (1.0f - x - RAD) - 0.5f;
    float hix = 64.0f * (1.0f - x + RAD) - 0.5f;
    float loy = 64.0f * (1.0f - y - RAD) - 0.5f;
    float hiy = 64.0f * (1.0f - y + RAD) - 0.5f;

    if (!(hix >= 0.0f) || !(lox <= (float)(WW - 1))) return;
    if (!(hiy >= 0.0f) || !(loy <= (float)(HH - 1))) return;

    int ix0 = max(0, (int)floorf(fmaxf(lox, 0.0f)));
    int ix1 = min(WW - 1, (int)ceilf(fminf(hix, (float)(WW - 1))));
    int iy0 = max(0, (int)floorf(fmaxf(loy, 0.0f)));
    int iy1 = min(HH - 1, (int)ceilf(fminf(hiy, (float)(HH - 1))));
    if (ix0 > ix1 || iy0 > iy1) return;

    int tx0 = ix0 >> 4, tx1 = ix1 >> 4;
    int ty0 = iy0 >> 4, ty1 = iy1 >> 4;

    float4 rec = make_float4(x, y, zv, (float)p);
    for (int ty = ty0; ty <= ty1; ty++) {
        for (int tx = tx0; tx <= tx1; tx++) {
            int tile = b * NTILES + ty * TX + tx;
            int pos = atomicAdd(&g_cnt[tile], 1);
            g_list[tile * NP + pos] = rec;
        }
    }
}

// ---------------------------------------------------------------------------
// Kernel B: per-tile raster. 512 threads = 2 threads/pixel, merged top-8.
// Re-zeroes its own tile counter for the next graph replay.
// ---------------------------------------------------------------------------
__global__ void __launch_bounds__(512) raster_kernel(float* __restrict__ out) {
    // smem: staging (CHUNK float4 = 8KB) reused later as merge area (24KB)
    __shared__ unsigned char smem_raw[3 * 256 * KK * sizeof(float)];
    float4* sc = (float4*)smem_raw;

    const int tx = blockIdx.x, ty = blockIdx.y, b = blockIdx.z;
    const int tid = threadIdx.x;
    const int pix = tid & 255;
    const int half = tid >> 8;

    const int tile = b * NTILES + ty * TX + tx;

    __shared__ int s_n;
    if (tid == 0) {
        s_n = g_cnt[tile];
        g_cnt[tile] = 0;      // reset for next replay (own counter only)
    }
    __syncthreads();
    const int n = s_n;
    const float4* __restrict__ list = g_list + tile * NP;

    const int lx = pix & 15, ly = pix >> 4;
    const int px = tx * TILE + lx;
    const int py = ty * TILE + ly;
    const float gx = 1.0f - (px + 0.5f) * (1.0f / 64.0f);
    const float gy = 1.0f - (py + 0.5f) * (1.0f / 64.0f);

    float zb[KK], db[KK], ib[KK];
#pragma unroll
    for (int k = 0; k < KK; k++) { zb[k] = ZINF; db[k] = -1.0f; ib[k] = -1.0f; }

    for (int base = 0; base < n; base += CHUNK) {
        int m = min(CHUNK, n - base);
        __syncthreads();
        if (tid < m) sc[tid] = list[base + tid];   // coalesced 16B loads
        __syncthreads();

        int j0 = half << 8;              // half 0: [0,256), half 1: [256,512)
        int j1 = min(m, j0 + 256);
#pragma unroll 4
        for (int j = j0; j < j1; j++) {
            float4 c = sc[j];            // LDS.128 broadcast within warp
            float dx = gx - c.x;
            float dy = gy - c.y;
            float d2 = fmaf(dx, dx, dy * dy);
            if (d2 < RAD2 && c.z < zb[KK - 1]) {
                float zi = c.z, di = d2, ii = c.w;
#pragma unroll
                for (int k = 0; k < KK; k++) {
                    if (zi < zb[k]) {
                        float t;
                        t = zb[k]; zb[k] = zi; zi = t;
                        t = db[k]; db[k] = di; di = t;
                        t = ib[k]; ib[k] = ii; ii = t;
                    }
                }
            }
        }
    }

    // ---- merge half 1's sorted top-8 into half 0's ----
    float* mzb = (float*)smem_raw;
    float* mdb = mzb + 256 * KK;
    float* mib = mdb + 256 * KK;
    __syncthreads();
    if (half == 1) {
#pragma unroll
        for (int k = 0; k < KK; k++) {
            mzb[pix * KK + k] = zb[k];
            mdb[pix * KK + k] = db[k];
            mib[pix * KK + k] = ib[k];
        }
    }
    __syncthreads();
    if (half == 0) {
#pragma unroll
        for (int k = 0; k < KK; k++) {
            float zi = mzb[pix * KK + k];
            if (!(zi < zb[KK - 1])) break;   // incoming sorted ascending
            float di = mdb[pix * KK + k];
            float ii = mib[pix * KK + k];
#pragma unroll
            for (int q = 0; q < KK; q++) {
                if (zi < zb[q]) {
                    float t;
                    t = zb[q]; zb[q] = zi; zi = t;
                    t = db[q]; db[q] = di; di = t;
                    t = ib[q]; ib[q] = ii; ii = t;
                }
            }
        }

        // ---- Output: [idx | zbuf | dists], each [B,H,W,K] ----
        const int N = BATCH * HH * WW * KK;
        const int obase = ((b * HH + py) * WW + px) * KK;
#pragma unroll
        for (int k = 0; k < KK; k++) {
            bool v = zb[k] < ZINF;
            out[obase + k]         = v ? ib[k] : -1.0f;
            out[N + obase + k]     = v ? zb[k] : -1.0f;
            out[2 * N + obase + k] = v ? db[k] : -1.0f;
        }
    }
}

// ---------------------------------------------------------------------------
extern "C" void kernel_launch(void* const* d_in, const int* in_sizes, int n_in,
                              void* d_out, int out_size) {
    const float* pts = (const float*)d_in[0];
    const float* Rm  = (const float*)d_in[1];
    const float* Tv  = (const float*)d_in[2];
    const float* Fc  = (const float*)d_in[3];
    float* out = (float*)d_out;

    transform_bin_kernel<<<(BATCH * NP + 255) / 256, 256>>>(pts, Rm, Tv, Fc);
    raster_kernel<<<dim3(TX, TYN, BATCH), 512>>>(out);
}